// round 1
// baseline (speedup 1.0000x reference)
#include <cuda_runtime.h>
#include <math.h>
#include <stdint.h>

#define DD 1024
#define NNODE 768
#define NEDGE 24576
#define SCALE 0.03125f   // 1/sqrt(1024)
#define FIXS 4294967296.0  // 2^32 fixed-point scale

// ---------------------------------------------------------------------------
// Scratch (static device memory -- no allocations allowed)
// ---------------------------------------------------------------------------
struct __align__(256) Scratch {
    float Ks[DD*DD], Ko[DD*DD], Ls[DD*DD], Lo[DD*DD], Us[DD*DD], Uo[DD*DD], Mq[DD*DD];
    float TSs[NNODE*DD], TSo[NNODE*DD], TOs[NNODE*DD], TOo[NNODE*DD], R1[NNODE*DD], R2[NNODE*DD];
    float cs[DD], co[DD];
    float a1[NNODE], a2[NNODE];
    float Cmat[NNODE*NNODE];
    float Z[(size_t)NEDGE*DD];
    float logits[NEDGE], es[NEDGE], eo[NEDGE];
    float invs[NNODE], invo[NNODE];
    float ctxf[NNODE*DD];
    unsigned long long sums[NNODE], sumo[NNODE];
    unsigned long long ctx[NNODE*DD];
    unsigned int maxs[NNODE], maxo[NNODE];
    int involved[NNODE];
};
__device__ Scratch g_s;

// ---------------------------------------------------------------------------
// Tiled SGEMM (row-major).  C[M,N] = A[M,K] @ op(B) (+ addend) (+ bias),
// with optional per-row mask epilogue: !mask -> C = elsemat.
// TRANSB: B given as (N,K) row-major, used transposed.
// Requires M%BM==0, N%BN==0, K%BK==0 (all shapes here satisfy this).
// ---------------------------------------------------------------------------
template<int BM, int BN, int BK, int TM, int TN, bool TRANSB>
__global__ __launch_bounds__(256)
void sgemm_k(const float* __restrict__ A, const float* __restrict__ B,
             float* __restrict__ C, int M, int N, int K,
             const float* __restrict__ addend,
             const float* __restrict__ bias,
             const int*   __restrict__ rowmask,
             const float* __restrict__ elsemat)
{
    static_assert(BM*BK/4 == 256 && BK*BN/4 == 256, "loader sized for 256 threads");
    __shared__ float As[BK][BM];
    __shared__ float Bs[BK][BN + 4];

    const int tid = threadIdx.x;
    const int block_row = blockIdx.y * BM;
    const int block_col = blockIdx.x * BN;

    const int NT_COL = BN / TN;
    const int trow = (tid / NT_COL) * TM;
    const int tcol = (tid % NT_COL) * TN;

    const int aRow = tid / (BK/4);
    const int aCol = (tid % (BK/4)) * 4;
    const int bRowNN = tid / (BN/4);
    const int bColNN = (tid % (BN/4)) * 4;
    const int bRowNT = tid / (BK/4);
    const int bColNT = (tid % (BK/4)) * 4;

    float acc[TM][TN];
    #pragma unroll
    for (int i = 0; i < TM; i++)
        #pragma unroll
        for (int j = 0; j < TN; j++) acc[i][j] = 0.f;

    for (int k0 = 0; k0 < K; k0 += BK) {
        float4 av = *reinterpret_cast<const float4*>(
            A + (size_t)(block_row + aRow) * K + k0 + aCol);
        As[aCol+0][aRow] = av.x;
        As[aCol+1][aRow] = av.y;
        As[aCol+2][aRow] = av.z;
        As[aCol+3][aRow] = av.w;
        if (!TRANSB) {
            float4 bv = *reinterpret_cast<const float4*>(
                B + (size_t)(k0 + bRowNN) * N + block_col + bColNN);
            Bs[bRowNN][bColNN+0] = bv.x;
            Bs[bRowNN][bColNN+1] = bv.y;
            Bs[bRowNN][bColNN+2] = bv.z;
            Bs[bRowNN][bColNN+3] = bv.w;
        } else {
            float4 bv = *reinterpret_cast<const float4*>(
                B + (size_t)(block_col + bRowNT) * K + k0 + bColNT);
            Bs[bColNT+0][bRowNT] = bv.x;
            Bs[bColNT+1][bRowNT] = bv.y;
            Bs[bColNT+2][bRowNT] = bv.z;
            Bs[bColNT+3][bRowNT] = bv.w;
        }
        __syncthreads();
        #pragma unroll
        for (int kk = 0; kk < BK; kk++) {
            float ra[TM], rb[TN];
            #pragma unroll
            for (int i = 0; i < TM; i++) ra[i] = As[kk][trow + i];
            #pragma unroll
            for (int j = 0; j < TN; j++) rb[j] = Bs[kk][tcol + j];
            #pragma unroll
            for (int i = 0; i < TM; i++)
                #pragma unroll
                for (int j = 0; j < TN; j++)
                    acc[i][j] = fmaf(ra[i], rb[j], acc[i][j]);
        }
        __syncthreads();
    }

    #pragma unroll
    for (int i = 0; i < TM; i++) {
        const int row = block_row + trow + i;
        const bool keep = rowmask ? (rowmask[row] != 0) : true;
        #pragma unroll
        for (int j = 0; j < TN; j++) {
            const int col = block_col + tcol + j;
            const size_t idx = (size_t)row * N + col;
            float v;
            if (keep) {
                v = acc[i][j];
                if (addend) v += addend[idx];
                if (bias)   v += bias[col];
            } else {
                v = elsemat[idx];
            }
            C[idx] = v;
        }
    }
}

// ---------------------------------------------------------------------------
// Small kernels
// ---------------------------------------------------------------------------
__device__ __forceinline__ float blockReduceSum(float v) {
    __shared__ float sh[8];
    __syncthreads();
    int lane = threadIdx.x & 31, w = threadIdx.x >> 5;
    #pragma unroll
    for (int o = 16; o > 0; o >>= 1) v += __shfl_down_sync(0xffffffffu, v, o);
    if (lane == 0) sh[w] = v;
    __syncthreads();
    v = (threadIdx.x < 8) ? sh[threadIdx.x] : 0.f;
    if (w == 0) {
        #pragma unroll
        for (int o = 4; o > 0; o >>= 1) v += __shfl_down_sync(0xffu, v, o);
    }
    return v;  // valid in thread 0
}

__device__ __forceinline__ unsigned int fenc(float f) {
    unsigned int u = __float_as_uint(f);
    return (u & 0x80000000u) ? ~u : (u | 0x80000000u);
}
__device__ __forceinline__ float fdec(unsigned int u) {
    return (u & 0x80000000u) ? __uint_as_float(u ^ 0x80000000u) : __uint_as_float(~u);
}
__device__ __forceinline__ unsigned long long fix64(float x) {
    return (unsigned long long)__double2ll_rn((double)x * FIXS);
}

__global__ void k_init(unsigned long long* ctx, unsigned long long* sums,
                       unsigned long long* sumo, unsigned int* maxs,
                       unsigned int* maxo, int* involved) {
    int i = blockIdx.x * blockDim.x + threadIdx.x;
    if (i < NNODE*DD) ctx[i] = 0ull;
    if (i < NNODE) { sums[i] = 0ull; sumo[i] = 0ull; maxs[i] = 0u; maxo[i] = 0u; involved[i] = 0; }
}

// out[j] = bias2[j] + sum_k b[k] * W[k,j]
__global__ void k_vecmat(const float* __restrict__ b, const float* __restrict__ W,
                         const float* __restrict__ bias2, float* __restrict__ outv) {
    int j = blockIdx.x * blockDim.x + threadIdx.x;
    if (j >= DD) return;
    float s = bias2[j];
    for (int k = 0; k < DD; k++) s = fmaf(b[k], W[(size_t)k*DD + j], s);
    outv[j] = s;
}

__global__ void k_dots(const float* __restrict__ TSs, const float* __restrict__ TOs,
                       const float* __restrict__ TSo, const float* __restrict__ TOo,
                       float* __restrict__ a1, float* __restrict__ a2) {
    int n = blockIdx.x;
    float p1 = 0.f, p2 = 0.f;
    for (int d = threadIdx.x; d < DD; d += blockDim.x) {
        p1 = fmaf(TSs[(size_t)n*DD+d], TOs[(size_t)n*DD+d], p1);
        p2 = fmaf(TSo[(size_t)n*DD+d], TOo[(size_t)n*DD+d], p2);
    }
    p1 = blockReduceSum(p1);
    p2 = blockReduceSum(p2);
    if (threadIdx.x == 0) { a1[n] = p1; a2[n] = p2; }
}

// logits[e] = SCALE * ( a1[s]+a2[o]+Cmat[s,o] + rvf_e . (Z_e + R1[s] + R2[o]) )
__global__ void k_logits(const float* __restrict__ rvf, const float* __restrict__ Z,
                         const float* __restrict__ R1, const float* __restrict__ R2,
                         const float* __restrict__ a1, const float* __restrict__ a2,
                         const float* __restrict__ Cmat,
                         const int* __restrict__ sbj, const int* __restrict__ obj,
                         float* __restrict__ logits) {
    int e = blockIdx.x;
    int s = sbj[e], o = obj[e];
    const float* r  = rvf + (size_t)e*DD;
    const float* z  = Z   + (size_t)e*DD;
    const float* r1 = R1  + (size_t)s*DD;
    const float* r2 = R2  + (size_t)o*DD;
    float p = 0.f;
    for (int d = threadIdx.x; d < DD; d += blockDim.x)
        p = fmaf(r[d], z[d] + r1[d] + r2[d], p);
    p = blockReduceSum(p);
    if (threadIdx.x == 0)
        logits[e] = (p + a1[s] + a2[o] + Cmat[(size_t)s*NNODE + o]) * SCALE;
}

__global__ void k_segmax(const float* __restrict__ logits, const int* __restrict__ sbj,
                         const int* __restrict__ obj, unsigned int* maxs,
                         unsigned int* maxo, int* involved) {
    int e = blockIdx.x * blockDim.x + threadIdx.x;
    if (e >= NEDGE) return;
    unsigned int u = fenc(logits[e]);
    int s = sbj[e], o = obj[e];
    atomicMax(&maxs[s], u);
    atomicMax(&maxo[o], u);
    involved[s] = 1;
    involved[o] = 1;
}

__global__ void k_exp(const float* __restrict__ logits, const int* __restrict__ sbj,
                      const int* __restrict__ obj, const unsigned int* __restrict__ maxs,
                      const unsigned int* __restrict__ maxo,
                      float* __restrict__ es, float* __restrict__ eo,
                      unsigned long long* sums, unsigned long long* sumo) {
    int e = blockIdx.x * blockDim.x + threadIdx.x;
    if (e >= NEDGE) return;
    int s = sbj[e], o = obj[e];
    float l = logits[e];
    float vs_ = expf(l - fdec(maxs[s]));
    float vo_ = expf(l - fdec(maxo[o]));
    es[e] = vs_;
    eo[e] = vo_;
    atomicAdd(&sums[s], fix64(vs_));
    atomicAdd(&sumo[o], fix64(vo_));
}

__global__ void k_inv(const unsigned long long* __restrict__ sums,
                      const unsigned long long* __restrict__ sumo,
                      float* __restrict__ invs, float* __restrict__ invo) {
    int n = blockIdx.x * blockDim.x + threadIdx.x;
    if (n >= NNODE) return;
    invs[n] = sums[n] ? (float)(FIXS / (double)sums[n]) : 0.f;
    invo[n] = sumo[n] ? (float)(FIXS / (double)sumo[n]) : 0.f;
}

// ctx[s] += w_sbj[e]*vf[o];  ctx[o] += w_obj[e]*vf[s]   (fixed-point, deterministic)
__global__ void k_ctx(const float* __restrict__ vf, const float* __restrict__ es,
                      const float* __restrict__ eo, const float* __restrict__ invs,
                      const float* __restrict__ invo, const int* __restrict__ sbj,
                      const int* __restrict__ obj, unsigned long long* ctx) {
    int e = blockIdx.x;
    int s = sbj[e], o = obj[e];
    float ws_ = es[e] * invs[s];
    float wo_ = eo[e] * invo[o];
    const float4* vo4 = reinterpret_cast<const float4*>(vf + (size_t)o*DD);
    const float4* vs4 = reinterpret_cast<const float4*>(vf + (size_t)s*DD);
    unsigned long long* cs_ = ctx + (size_t)s*DD;
    unsigned long long* co_ = ctx + (size_t)o*DD;
    int t = threadIdx.x;          // 256 threads * float4 = 1024
    float4 a = vo4[t];
    float4 b = vs4[t];
    int d = t * 4;
    atomicAdd(&cs_[d+0], fix64(ws_ * a.x));
    atomicAdd(&cs_[d+1], fix64(ws_ * a.y));
    atomicAdd(&cs_[d+2], fix64(ws_ * a.z));
    atomicAdd(&cs_[d+3], fix64(ws_ * a.w));
    atomicAdd(&co_[d+0], fix64(wo_ * b.x));
    atomicAdd(&co_[d+1], fix64(wo_ * b.y));
    atomicAdd(&co_[d+2], fix64(wo_ * b.z));
    atomicAdd(&co_[d+3], fix64(wo_ * b.w));
}

__global__ void k_cvt(const unsigned long long* __restrict__ ctx, float* __restrict__ ctxf) {
    int i = blockIdx.x * blockDim.x + threadIdx.x;
    if (i < NNODE*DD)
        ctxf[i] = (float)((double)(long long)ctx[i] * (1.0 / FIXS));
}

// ---------------------------------------------------------------------------
// Host orchestration
// ---------------------------------------------------------------------------
static inline void G64(const float* A, const float* B, float* C, int M, int N,
                       bool transB, const float* add = nullptr,
                       const float* bias = nullptr, const int* rm = nullptr,
                       const float* els = nullptr) {
    dim3 g(N/64, M/64);
    if (transB)
        sgemm_k<64,64,16,4,4,true ><<<g,256>>>(A,B,C,M,N,DD,add,bias,rm,els);
    else
        sgemm_k<64,64,16,4,4,false><<<g,256>>>(A,B,C,M,N,DD,add,bias,rm,els);
}

static inline void G128(const float* A, const float* B, float* C, int M, int N) {
    dim3 g(N/128, M/128);
    sgemm_k<128,128,8,8,8,false><<<g,256>>>(A,B,C,M,N,DD,nullptr,nullptr,nullptr,nullptr);
}

extern "C" void kernel_launch(void* const* d_in, const int* in_sizes, int n_in,
                              void* d_out, int out_size) {
    (void)in_sizes; (void)n_in; (void)out_size;
    const float* vf    = (const float*)d_in[0];
    const float* rvf   = (const float*)d_in[1];
    const float* W_rel = (const float*)d_in[2];
    const float* b_rel = (const float*)d_in[3];
    const float* W_sbj = (const float*)d_in[4];
    const float* b_sbj = (const float*)d_in[5];
    const float* W_obj = (const float*)d_in[6];
    const float* b_obj = (const float*)d_in[7];
    const float* W_ctx = (const float*)d_in[8];
    const float* b_ctx = (const float*)d_in[9];
    const int*   sbj   = (const int*)d_in[10];
    const int*   obj   = (const int*)d_in[11];
    float* out = (float*)d_out;
    float* out_vj = out + (size_t)NEDGE * DD;

    void* sp = nullptr;
    cudaGetSymbolAddress(&sp, g_s);
    Scratch* S = (Scratch*)sp;

    const float* Wr_s = W_rel;
    const float* Wr_o = W_rel + (size_t)DD*DD;
    const float* Wr_r = W_rel + 2*(size_t)DD*DD;
    const float* Ws_v = W_sbj;
    const float* Ws_r = W_sbj + (size_t)DD*DD;
    const float* Wo_v = W_obj;
    const float* Wo_r = W_obj + (size_t)DD*DD;

    // output part 1: rel_visual_feat passthrough
    cudaMemcpyAsync(out, rvf, (size_t)NEDGE*DD*sizeof(float),
                    cudaMemcpyDeviceToDevice);

    k_init<<<(NNODE*DD)/256, 256>>>(S->ctx, S->sums, S->sumo, S->maxs, S->maxo, S->involved);

    // bias composites
    k_vecmat<<<DD/256, 256>>>(b_rel, Ws_r, b_sbj, S->cs);
    k_vecmat<<<DD/256, 256>>>(b_rel, Wo_r, b_obj, S->co);

    // weight composites (D x D)
    G64(Wr_s, Ws_r, S->Ks, DD, DD, false, Ws_v);   // Ks = Ws_v + Wr_s@Ws_r
    G64(Wr_o, Ws_r, S->Ko, DD, DD, false);         // Ko = Wr_o@Ws_r
    G64(Wr_s, Wo_r, S->Ls, DD, DD, false);         // Ls = Wr_s@Wo_r
    G64(Wr_o, Wo_r, S->Lo, DD, DD, false, Wo_v);   // Lo = Wo_v + Wr_o@Wo_r
    G64(Wr_r, Ws_r, S->Us, DD, DD, false);         // Us = Wr_r@Ws_r
    G64(Wr_r, Wo_r, S->Uo, DD, DD, false);         // Uo = Wr_r@Wo_r
    G64(S->Us, S->Uo, S->Mq, DD, DD, true);        // Mq = Us @ Uo^T

    // node-side precomputes (N x D)
    G64(vf, S->Ks, S->TSs, NNODE, DD, false, nullptr, S->cs);  // TSs = vf@Ks + cs
    G64(vf, S->Ko, S->TSo, NNODE, DD, false);
    G64(vf, S->Ls, S->TOs, NNODE, DD, false, nullptr, S->co);  // TOs = vf@Ls + co
    G64(vf, S->Lo, S->TOo, NNODE, DD, false);

    G64(S->TSs, S->Uo, S->R1, NNODE, DD, true);                // R1  = TSs@Uo^T
    G64(S->TOs, S->Us, S->R1, NNODE, DD, true, S->R1);         // R1 += TOs@Us^T
    G64(S->TSo, S->Uo, S->R2, NNODE, DD, true);                // R2  = TSo@Uo^T
    G64(S->TOo, S->Us, S->R2, NNODE, DD, true, S->R2);         // R2 += TOo@Us^T

    G64(S->TSs, S->TOo, S->Cmat, NNODE, NNODE, true);              // Cmat  = TSs@TOo^T
    G64(S->TOs, S->TSo, S->Cmat, NNODE, NNODE, true, S->Cmat);     // Cmat += TOs@TSo^T

    k_dots<<<NNODE, 256>>>(S->TSs, S->TOs, S->TSo, S->TOo, S->a1, S->a2);

    // the one big GEMM: quadratic-form intermediate
    G128(rvf, S->Mq, S->Z, NEDGE, DD);

    // logits + edge softmax (deterministic)
    k_logits<<<NEDGE, 256>>>(rvf, S->Z, S->R1, S->R2, S->a1, S->a2, S->Cmat,
                             sbj, obj, S->logits);
    k_segmax<<<NEDGE/256, 256>>>(S->logits, sbj, obj, S->maxs, S->maxo, S->involved);
    k_exp<<<NEDGE/256, 256>>>(S->logits, sbj, obj, S->maxs, S->maxo,
                              S->es, S->eo, S->sums, S->sumo);
    k_inv<<<(NNODE+255)/256, 256>>>(S->sums, S->sumo, S->invs, S->invo);

    // context aggregation (fixed-point atomics -> deterministic)
    k_ctx<<<NEDGE, 256>>>(vf, S->es, S->eo, S->invs, S->invo, sbj, obj, S->ctx);
    k_cvt<<<(NNODE*DD)/256, 256>>>(S->ctx, S->ctxf);

    // vj = involved ? vf + ctx@W_ctx + b_ctx : vf   (written straight into d_out)
    G64(S->ctxf, W_ctx, out_vj, NNODE, DD, false, vf, b_ctx, S->involved, vf);
}

// round 4
// speedup vs baseline: 1.2932x; 1.2932x over previous
#include <cuda_runtime.h>
#include <math.h>
#include <stdint.h>

#define DD 1024
#define NNODE 768
#define NEDGE 24576
#define SCALE 0.03125f   // 1/sqrt(1024)

// ---------------------------------------------------------------------------
// Scratch (static device memory -- no allocations allowed)
// Layout: TS4 = [TSs | TOs | TOo | TSo]  (768 x 4096)
//         K4  = [Ks  | Ls  | Lo  | Ko ]  (1024 x 4096)  so TS4 = vf @ K4 + bias4
//         UUa = [Uo | Us], UUb = [Us | Uo]   (1024 x 2048)
// ---------------------------------------------------------------------------
struct __align__(256) Scratch {
    float Z[(size_t)NEDGE*DD];          // 100 MB
    float K4[(size_t)DD*4*DD];
    float UUa[(size_t)DD*2*DD];
    float UUb[(size_t)DD*2*DD];
    float Mq[(size_t)DD*DD];
    float TS4[(size_t)NNODE*4*DD];
    float R1[(size_t)NNODE*DD];
    float R2[(size_t)NNODE*DD];
    float Cmat[NNODE*NNODE];
    float ctxf[NNODE*DD];
    float bias4[4*DD];
    float logits[NEDGE], ws[NEDGE], wo[NEDGE];
    float a1[NNODE], a2[NNODE];
    int   startS[NNODE+8];
    int   startO[NNODE+8];
    int   cntO[NNODE];
    int   objlist[NEDGE];
    int   involved[NNODE];
};
__device__ Scratch g_s;

// ---------------------------------------------------------------------------
// Flexible z-batched tiled SGEMM with double-buffered smem + register prefetch.
// C[M,N] = A[M,K] @ op(B) (+addend) (+bias); optional dup-store C2; optional
// per-row mask epilogue (!mask -> C = els).
// ---------------------------------------------------------------------------
struct GDesc {
    const float* A; const float* B; float* C; float* C2;
    const float* add; const float* bias; const int* rowmask; const float* els;
    int lda, ldb, ldc, ldadd;
};
struct GParams {
    GDesc d[6];
    int M, N, K;
};

template<int BM, int BN, int BK, int TM, int TN, bool TRANSB>
__global__ __launch_bounds__(256)
void gemm_k(GParams p)
{
    const GDesc g = p.d[blockIdx.z];
    const int K = p.K;

    __shared__ float As[2][BK][BM];
    __shared__ float Bs[2][BK][BN + 4];

    const int tid = threadIdx.x;
    const int block_row = blockIdx.y * BM;
    const int block_col = blockIdx.x * BN;

    const int NT_COL = BN / TN;
    const int trow = (tid / NT_COL) * TM;
    const int tcol = (tid % NT_COL) * TN;

    constexpr int A_ITERS = (BM * BK) / (256 * 4);
    constexpr int B_ITERS = (BN * BK) / (256 * 4);

    float acc[TM][TN];
    #pragma unroll
    for (int i = 0; i < TM; i++)
        #pragma unroll
        for (int j = 0; j < TN; j++) acc[i][j] = 0.f;

    float4 pa[A_ITERS], pb[B_ITERS];

    // ---- prefetch helpers (global -> regs) ----
    auto fetch = [&](int k0) {
        #pragma unroll
        for (int it = 0; it < A_ITERS; it++) {
            int idx = tid + it * 256;
            int r = idx / (BK / 4);
            int c4 = (idx % (BK / 4)) * 4;
            pa[it] = *reinterpret_cast<const float4*>(
                g.A + (size_t)(block_row + r) * g.lda + k0 + c4);
        }
        #pragma unroll
        for (int it = 0; it < B_ITERS; it++) {
            int idx = tid + it * 256;
            if (!TRANSB) {
                int r = idx / (BN / 4);
                int c4 = (idx % (BN / 4)) * 4;
                pb[it] = *reinterpret_cast<const float4*>(
                    g.B + (size_t)(k0 + r) * g.ldb + block_col + c4);
            } else {
                int r = idx / (BK / 4);
                int c4 = (idx % (BK / 4)) * 4;
                pb[it] = *reinterpret_cast<const float4*>(
                    g.B + (size_t)(block_col + r) * g.ldb + k0 + c4);
            }
        }
    };
    auto stash = [&](int buf) {
        #pragma unroll
        for (int it = 0; it < A_ITERS; it++) {
            int idx = tid + it * 256;
            int r = idx / (BK / 4);
            int c4 = (idx % (BK / 4)) * 4;
            As[buf][c4+0][r] = pa[it].x; As[buf][c4+1][r] = pa[it].y;
            As[buf][c4+2][r] = pa[it].z; As[buf][c4+3][r] = pa[it].w;
        }
        #pragma unroll
        for (int it = 0; it < B_ITERS; it++) {
            int idx = tid + it * 256;
            if (!TRANSB) {
                int r = idx / (BN / 4);
                int c4 = (idx % (BN / 4)) * 4;
                Bs[buf][r][c4+0] = pb[it].x; Bs[buf][r][c4+1] = pb[it].y;
                Bs[buf][r][c4+2] = pb[it].z; Bs[buf][r][c4+3] = pb[it].w;
            } else {
                int r = idx / (BK / 4);
                int c4 = (idx % (BK / 4)) * 4;
                Bs[buf][c4+0][r] = pb[it].x; Bs[buf][c4+1][r] = pb[it].y;
                Bs[buf][c4+2][r] = pb[it].z; Bs[buf][c4+3][r] = pb[it].w;
            }
        }
    };

    const int NTILE = K / BK;
    int buf = 0;
    fetch(0);
    stash(0);
    __syncthreads();

    for (int t = 0; t < NTILE; t++) {
        if (t + 1 < NTILE) fetch((t + 1) * BK);
        #pragma unroll
        for (int kk = 0; kk < BK; kk++) {
            float ra[TM], rb[TN];
            #pragma unroll
            for (int i = 0; i < TM; i++) ra[i] = As[buf][kk][trow + i];
            #pragma unroll
            for (int j = 0; j < TN; j++) rb[j] = Bs[buf][kk][tcol + j];
            #pragma unroll
            for (int i = 0; i < TM; i++)
                #pragma unroll
                for (int j = 0; j < TN; j++)
                    acc[i][j] = fmaf(ra[i], rb[j], acc[i][j]);
        }
        if (t + 1 < NTILE) {
            stash(buf ^ 1);          // other buffer: fully consumed in iter t-1
            __syncthreads();
            buf ^= 1;
        }
    }

    #pragma unroll
    for (int i = 0; i < TM; i++) {
        const int row = block_row + trow + i;
        const bool keep = g.rowmask ? (g.rowmask[row] != 0) : true;
        #pragma unroll
        for (int j = 0; j < TN; j++) {
            const int col = block_col + tcol + j;
            float v;
            if (keep) {
                v = acc[i][j];
                if (g.add)  v += g.add[(size_t)row * g.ldadd + col];
                if (g.bias) v += g.bias[col];
            } else {
                v = g.els[(size_t)row * g.ldadd + col];
            }
            g.C[(size_t)row * g.ldc + col] = v;
            if (g.C2) g.C2[(size_t)row * g.ldc + col] = v;
        }
    }
}

// ---------------------------------------------------------------------------
// Small kernels
// ---------------------------------------------------------------------------
__device__ __forceinline__ float blockReduceSum(float v) {
    __shared__ float sh[8];
    __syncthreads();
    int lane = threadIdx.x & 31, w = threadIdx.x >> 5;
    #pragma unroll
    for (int o = 16; o > 0; o >>= 1) v += __shfl_down_sync(0xffffffffu, v, o);
    if (lane == 0) sh[w] = v;
    __syncthreads();
    v = (threadIdx.x < 8) ? sh[threadIdx.x] : 0.f;
    if (w == 0) {
        #pragma unroll
        for (int o = 4; o > 0; o >>= 1) v += __shfl_down_sync(0xffu, v, o);
    }
    return v;  // thread 0
}

// startS[n] = lower_bound(sbj, n)   (edges are sorted by sbj)
__global__ void k_startS(const int* __restrict__ sbj, int* __restrict__ startS) {
    int n = blockIdx.x * blockDim.x + threadIdx.x;
    if (n > NNODE) return;
    int lo = 0, hi = NEDGE;
    while (lo < hi) { int mid = (lo + hi) >> 1; if (sbj[mid] < n) lo = mid + 1; else hi = mid; }
    startS[n] = lo;
}

__global__ void k_cntO(const int* __restrict__ obj, int* __restrict__ cntO) {
    int n = blockIdx.x;
    int c = 0;
    for (int e = threadIdx.x; e < NEDGE; e += 256) c += (obj[e] == n);
    __shared__ int sh[8];
    int lane = threadIdx.x & 31, w = threadIdx.x >> 5;
    #pragma unroll
    for (int o = 16; o > 0; o >>= 1) c += __shfl_down_sync(0xffffffffu, c, o);
    if (lane == 0) sh[w] = c;
    __syncthreads();
    if (threadIdx.x == 0) {
        int t = 0;
        #pragma unroll
        for (int i = 0; i < 8; i++) t += sh[i];
        cntO[n] = t;
    }
}

__global__ void k_scanO(const int* __restrict__ cntO, int* __restrict__ startO) {
    __shared__ int sh[1024];
    int t = threadIdx.x;
    sh[t] = (t < NNODE) ? cntO[t] : 0;
    __syncthreads();
    #pragma unroll
    for (int off = 1; off < 1024; off <<= 1) {
        int v = (t >= off) ? sh[t - off] : 0;
        __syncthreads();
        sh[t] += v;
        __syncthreads();
    }
    if (t == 0) startO[0] = 0;
    if (t < NNODE) startO[t + 1] = sh[t];
}

// Stable (e-ordered) fill of per-obj edge lists. Deterministic: ballot order.
__global__ void k_fillO(const int* __restrict__ obj, const int* __restrict__ startO,
                        int* __restrict__ objlist) {
    int n = blockIdx.x;
    int base = startO[n];
    __shared__ int warpcnt[8];
    __shared__ int running;
    int tid = threadIdx.x, lane = tid & 31, w = tid >> 5;
    if (tid == 0) running = 0;
    __syncthreads();
    for (int e0 = 0; e0 < NEDGE; e0 += 256) {
        int e = e0 + tid;
        bool m = (obj[e] == n);
        unsigned bal = __ballot_sync(0xffffffffu, m);
        int wp = __popc(bal & ((1u << lane) - 1u));
        if (lane == 0) warpcnt[w] = __popc(bal);
        __syncthreads();
        int woff = 0, tot = 0;
        #pragma unroll
        for (int i = 0; i < 8; i++) { if (i < w) woff += warpcnt[i]; tot += warpcnt[i]; }
        if (m) objlist[base + running + woff + wp] = e;
        __syncthreads();
        if (tid == 0) running += tot;
        __syncthreads();
    }
}

__global__ void k_involved(const int* __restrict__ startS, const int* __restrict__ startO,
                           int* __restrict__ involved) {
    int n = blockIdx.x * blockDim.x + threadIdx.x;
    if (n >= NNODE) return;
    involved[n] = ((startS[n+1] - startS[n]) + (startO[n+1] - startO[n])) > 0;
}

// bias4 = [cs | co | 0 | 0]; cs = b_rel@Ws_r + b_sbj, co = b_rel@Wo_r + b_obj
__global__ void k_bias4(const float* __restrict__ b_rel,
                        const float* __restrict__ Ws_r, const float* __restrict__ Wo_r,
                        const float* __restrict__ b_sbj, const float* __restrict__ b_obj,
                        float* __restrict__ bias4) {
    int j = blockIdx.x * blockDim.x + threadIdx.x;
    if (j >= 4 * DD) return;
    if (j < DD) {
        float s = b_sbj[j];
        for (int k = 0; k < DD; k++) s = fmaf(b_rel[k], Ws_r[(size_t)k*DD + j], s);
        bias4[j] = s;
    } else if (j < 2 * DD) {
        int c = j - DD;
        float s = b_obj[c];
        for (int k = 0; k < DD; k++) s = fmaf(b_rel[k], Wo_r[(size_t)k*DD + c], s);
        bias4[j] = s;
    } else {
        bias4[j] = 0.f;
    }
}

// a1[n] = TSs[n].TOs[n], a2[n] = TSo[n].TOo[n]    (TS4 layout strided 4*DD)
__global__ void k_dots(const float* __restrict__ TS4,
                       float* __restrict__ a1, float* __restrict__ a2) {
    int n = blockIdx.x;
    const float* r = TS4 + (size_t)n * 4 * DD;
    float p1 = 0.f, p2 = 0.f;
    for (int d = threadIdx.x; d < DD; d += blockDim.x) {
        p1 = fmaf(r[d],        r[DD + d],   p1);   // TSs . TOs
        p2 = fmaf(r[3*DD + d], r[2*DD + d], p2);   // TSo . TOo
    }
    p1 = blockReduceSum(p1);
    p2 = blockReduceSum(p2);
    if (threadIdx.x == 0) { a1[n] = p1; a2[n] = p2; }
}

// logits[e] = SCALE * ( a1[s]+a2[o]+Cmat[s,o] + rvf_e . (Z_e + R1[s] + R2[o]) )
__global__ void k_logits(const float* __restrict__ rvf, const float* __restrict__ Z,
                         const float* __restrict__ R1, const float* __restrict__ R2,
                         const float* __restrict__ a1, const float* __restrict__ a2,
                         const float* __restrict__ Cmat,
                         const int* __restrict__ sbj, const int* __restrict__ obj,
                         float* __restrict__ logits) {
    int e = blockIdx.x;
    int s = sbj[e], o = obj[e];
    const float* r  = rvf + (size_t)e*DD;
    const float* z  = Z   + (size_t)e*DD;
    const float* r1 = R1  + (size_t)s*DD;
    const float* r2 = R2  + (size_t)o*DD;
    float p = 0.f;
    for (int d = threadIdx.x; d < DD; d += blockDim.x)
        p = fmaf(r[d], z[d] + r1[d] + r2[d], p);
    p = blockReduceSum(p);
    if (threadIdx.x == 0)
        logits[e] = (p + a1[s] + a2[o] + Cmat[(size_t)s*NNODE + o]) * SCALE;
}

// Segment softmax over sbj ranges (direct) -- one warp per node, no atomics.
__global__ void k_soft_s(const float* __restrict__ logits, const int* __restrict__ startS,
                         float* __restrict__ ws) {
    int n = blockIdx.x * 8 + (threadIdx.x >> 5);
    if (n >= NNODE) return;
    int lane = threadIdx.x & 31;
    int b = startS[n], t = startS[n+1];
    float mx = -INFINITY;
    for (int i = b + lane; i < t; i += 32) mx = fmaxf(mx, logits[i]);
    #pragma unroll
    for (int o = 16; o > 0; o >>= 1) mx = fmaxf(mx, __shfl_xor_sync(0xffffffffu, mx, o));
    float s = 0.f;
    for (int i = b + lane; i < t; i += 32) s += expf(logits[i] - mx);
    #pragma unroll
    for (int o = 16; o > 0; o >>= 1) s += __shfl_xor_sync(0xffffffffu, s, o);
    float inv = 1.f / s;
    for (int i = b + lane; i < t; i += 32) ws[i] = expf(logits[i] - mx) * inv;
}

// Segment softmax over obj (indirect via objlist).
__global__ void k_soft_o(const float* __restrict__ logits, const int* __restrict__ startO,
                         const int* __restrict__ objlist, float* __restrict__ wo) {
    int n = blockIdx.x * 8 + (threadIdx.x >> 5);
    if (n >= NNODE) return;
    int lane = threadIdx.x & 31;
    int b = startO[n], t = startO[n+1];
    float mx = -INFINITY;
    for (int i = b + lane; i < t; i += 32) mx = fmaxf(mx, logits[objlist[i]]);
    #pragma unroll
    for (int o = 16; o > 0; o >>= 1) mx = fmaxf(mx, __shfl_xor_sync(0xffffffffu, mx, o));
    float s = 0.f;
    for (int i = b + lane; i < t; i += 32) s += expf(logits[objlist[i]] - mx);
    #pragma unroll
    for (int o = 16; o > 0; o >>= 1) s += __shfl_xor_sync(0xffffffffu, s, o);
    float inv = 1.f / s;
    for (int i = b + lane; i < t; i += 32) {
        int e = objlist[i];
        wo[e] = expf(logits[e] - mx) * inv;
    }
}

// ctx[n] = sum_{e in sbjseg(n)} ws[e] * vf[obj[e]]      (write)
__global__ void k_ctx_s(const float4* __restrict__ vf4, const float* __restrict__ ws,
                        const int* __restrict__ obj, const int* __restrict__ startS,
                        float4* __restrict__ ctx4) {
    int n = blockIdx.x, t = threadIdx.x;   // 256 threads, each owns a float4
    int b = startS[n], e_t = startS[n+1];
    float4 acc = {0.f, 0.f, 0.f, 0.f};
    for (int i = b; i < e_t; i++) {
        float w = ws[i];
        float4 v = vf4[(size_t)obj[i] * 256 + t];
        acc.x = fmaf(w, v.x, acc.x); acc.y = fmaf(w, v.y, acc.y);
        acc.z = fmaf(w, v.z, acc.z); acc.w = fmaf(w, v.w, acc.w);
    }
    ctx4[(size_t)n * 256 + t] = acc;
}

// ctx[n] += sum_{e in objseg(n)} wo[e] * vf[sbj[e]]     (accumulate)
__global__ void k_ctx_o(const float4* __restrict__ vf4, const float* __restrict__ wo,
                        const int* __restrict__ sbj, const int* __restrict__ startO,
                        const int* __restrict__ objlist, float4* __restrict__ ctx4) {
    int n = blockIdx.x, t = threadIdx.x;
    int b = startO[n], e_t = startO[n+1];
    float4 acc = ctx4[(size_t)n * 256 + t];
    for (int i = b; i < e_t; i++) {
        int e = objlist[i];
        float w = wo[e];
        float4 v = vf4[(size_t)sbj[e] * 256 + t];
        acc.x = fmaf(w, v.x, acc.x); acc.y = fmaf(w, v.y, acc.y);
        acc.z = fmaf(w, v.z, acc.z); acc.w = fmaf(w, v.w, acc.w);
    }
    ctx4[(size_t)n * 256 + t] = acc;
}

// ---------------------------------------------------------------------------
// Host orchestration
// ---------------------------------------------------------------------------
static inline GDesc mkd(const float* A, int lda, const float* B, int ldb,
                        float* C, int ldc, float* C2 = nullptr,
                        const float* add = nullptr, int ldadd = 0,
                        const float* bias = nullptr,
                        const int* rm = nullptr, const float* els = nullptr) {
    GDesc d; d.A = A; d.B = B; d.C = C; d.C2 = C2; d.add = add; d.bias = bias;
    d.rowmask = rm; d.els = els; d.lda = lda; d.ldb = ldb; d.ldc = ldc; d.ldadd = ldadd;
    return d;
}

extern "C" void kernel_launch(void* const* d_in, const int* in_sizes, int n_in,
                              void* d_out, int out_size) {
    (void)in_sizes; (void)n_in; (void)out_size;
    const float* vf    = (const float*)d_in[0];
    const float* rvf   = (const float*)d_in[1];
    const float* W_rel = (const float*)d_in[2];
    const float* b_rel = (const float*)d_in[3];
    const float* W_sbj = (const float*)d_in[4];
    const float* b_sbj = (const float*)d_in[5];
    const float* W_obj = (const float*)d_in[6];
    const float* b_obj = (const float*)d_in[7];
    const float* W_ctx = (const float*)d_in[8];
    const float* b_ctx = (const float*)d_in[9];
    const int*   sbj   = (const int*)d_in[10];
    const int*   obj   = (const int*)d_in[11];
    float* out = (float*)d_out;
    float* out_vj = out + (size_t)NEDGE * DD;

    void* sp = nullptr;
    cudaGetSymbolAddress(&sp, g_s);
    Scratch* S = (Scratch*)sp;

    const float* Wr_s = W_rel;
    const float* Wr_o = W_rel + (size_t)DD*DD;
    const float* Wr_r = W_rel + 2*(size_t)DD*DD;
    const float* Ws_v = W_sbj;
    const float* Ws_r = W_sbj + (size_t)DD*DD;
    const float* Wo_v = W_obj;
    const float* Wo_r = W_obj + (size_t)DD*DD;

    // output part 1: rel_visual_feat passthrough
    cudaMemcpyAsync(out, rvf, (size_t)NEDGE*DD*sizeof(float),
                    cudaMemcpyDeviceToDevice);

    // ---- CSR construction (int-only, deterministic) ----
    k_startS<<<4, 256>>>(sbj, S->startS);
    k_cntO<<<NNODE, 256>>>(obj, S->cntO);
    k_scanO<<<1, 1024>>>(S->cntO, S->startO);
    k_fillO<<<NNODE, 256>>>(obj, S->startO, S->objlist);
    k_involved<<<3, 256>>>(S->startS, S->startO, S->involved);

    k_bias4<<<16, 256>>>(b_rel, Ws_r, Wo_r, b_sbj, b_obj, S->bias4);

    // ---- 6 weight composites in ONE z-batched GEMM ----
    // K4 = [Ks | Ls | Lo | Ko]; Us -> UUb[:,0:D] & UUa[:,D:2D]; Uo -> UUa[:,0:D] & UUb[:,D:2D]
    {
        GParams p; p.M = DD; p.N = DD; p.K = DD;
        p.d[0] = mkd(Wr_s, DD, Ws_r, DD, S->K4 + 0,      4*DD, nullptr, Ws_v, DD); // Ks
        p.d[1] = mkd(Wr_s, DD, Wo_r, DD, S->K4 + DD,     4*DD);                     // Ls
        p.d[2] = mkd(Wr_o, DD, Wo_r, DD, S->K4 + 2*DD,   4*DD, nullptr, Wo_v, DD); // Lo
        p.d[3] = mkd(Wr_o, DD, Ws_r, DD, S->K4 + 3*DD,   4*DD);                     // Ko
        p.d[4] = mkd(Wr_r, DD, Ws_r, DD, S->UUb + 0,     2*DD, S->UUa + DD);        // Us
        p.d[5] = mkd(Wr_r, DD, Wo_r, DD, S->UUa + 0,     2*DD, S->UUb + DD);        // Uo
        dim3 grid(DD/128, DD/128, 6);
        gemm_k<128,128,16,8,8,false><<<grid, 256>>>(p);
    }

    // ---- Mq = Us @ Uo^T ----
    {
        GParams p; p.M = DD; p.N = DD; p.K = DD;
        p.d[0] = mkd(S->UUb, 2*DD, S->UUa, 2*DD, S->Mq, DD);
        dim3 grid(DD/64, DD/64, 1);
        gemm_k<64,64,16,4,4,true><<<grid, 256>>>(p);
    }

    // ---- TS4 = vf @ K4 + bias4   (768 x 4096) ----
    {
        GParams p; p.M = NNODE; p.N = 4*DD; p.K = DD;
        p.d[0] = mkd(vf, DD, S->K4, 4*DD, S->TS4, 4*DD, nullptr, nullptr, 0, S->bias4);
        dim3 grid((4*DD)/128, NNODE/128, 1);
        gemm_k<128,128,16,8,8,false><<<grid, 256>>>(p);
    }

    // ---- R1 = [TSs TOs] @ UUa^T ;  R2 = [TOo TSo] @ UUb^T   (z-batched, K=2D) ----
    {
        GParams p; p.M = NNODE; p.N = DD; p.K = 2*DD;
        p.d[0] = mkd(S->TS4 + 0,    4*DD, S->UUa, 2*DD, S->R1, DD);
        p.d[1] = mkd(S->TS4 + 2*DD, 4*DD, S->UUb, 2*DD, S->R2, DD);
        dim3 grid(DD/64, NNODE/64, 2);
        gemm_k<64,64,16,4,4,true><<<grid, 256>>>(p);
    }

    // ---- Cmat = [TSs TOs] @ [TOo TSo]^T   (K=2D) ----
    {
        GParams p; p.M = NNODE; p.N = NNODE; p.K = 2*DD;
        p.d[0] = mkd(S->TS4 + 0, 4*DD, S->TS4 + 2*DD, 4*DD, S->Cmat, NNODE);
        dim3 grid(NNODE/64, NNODE/64, 1);
        gemm_k<64,64,16,4,4,true><<<grid, 256>>>(p);
    }

    k_dots<<<NNODE, 256>>>(S->TS4, S->a1, S->a2);

    // ---- the one big GEMM: Z = rvf @ Mq   (24576 x 1024 x 1024) ----
    {
        GParams p; p.M = NEDGE; p.N = DD; p.K = DD;
        p.d[0] = mkd(rvf, DD, S->Mq, DD, S->Z, DD);
        dim3 grid(DD/128, NEDGE/128, 1);
        gemm_k<128,128,16,8,8,false><<<grid, 256>>>(p);
    }

    // ---- logits + CSR softmax + ctx (no atomics, deterministic order) ----
    k_logits<<<NEDGE, 256>>>(rvf, S->Z, S->R1, S->R2, S->a1, S->a2, S->Cmat,
                             sbj, obj, S->logits);
    k_soft_s<<<NNODE/8, 256>>>(S->logits, S->startS, S->ws);
    k_soft_o<<<NNODE/8, 256>>>(S->logits, S->startO, S->objlist, S->wo);
    k_ctx_s<<<NNODE, 256>>>((const float4*)vf, S->ws, obj, S->startS, (float4*)S->ctxf);
    k_ctx_o<<<NNODE, 256>>>((const float4*)vf, S->wo, sbj, S->startO, S->objlist,
                            (float4*)S->ctxf);

    // ---- vj = involved ? vf + ctx@W_ctx + b_ctx : vf ----
    {
        GParams p; p.M = NNODE; p.N = DD; p.K = DD;
        p.d[0] = mkd(S->ctxf, DD, W_ctx, DD, out_vj, DD, nullptr,
                     vf, DD, b_ctx, S->involved, vf);
        dim3 grid(DD/64, NNODE/64, 1);
        gemm_k<64,64,16,4,4,false><<<grid, 256>>>(p);
    }
}